// round 15
// baseline (speedup 1.0000x reference)
#include <cuda_runtime.h>
#include <cuda_fp16.h>
#include <cstdint>
#include <math.h>

#define BB 8
#define TT 1024
#define DD 512
#define HH 8
#define FF 2048
#define MM (BB*TT)   // 8192 rows
#define NQKV (3*DD)  // 1536

// ---------------- scratch (allocation-free: __device__ globals) ----------------
__device__ __half g_h16[MM*DD];       // LN(x) in fp16 (feeds QKV GEMM)
__device__ __half g_qkv16[MM*NQKV];   // fused QKV output, fp16
__device__ float  g_attn[MM*DD];      // attention output (pre-residual)
__device__ float  g_a[MM*DD];         // LN1(attn + x) fp32 (LN2 residual)
__device__ __half g_a16[MM*DD];       // LN1 fp16 (feeds FFN1)
__device__ __half g_f116[MM*FF];      // relu(a@W1+b1) fp16 (feeds FFN2)
__device__ float  g_f2[MM*DD];        // f1@W2+b2
__device__ __half g_Wqkvt16[NQKV*DD]; // [1536,512] fp16, rows q|k|v, transposed
__device__ __half g_W1t16[FF*DD];     // [2048,512] fp16
__device__ __half g_W2t16[DD*FF];     // [512,2048] fp16
__device__ float  g_bqkv[NQKV];

// ---------------- helpers ----------------
__device__ __forceinline__ uint32_t s2u(const void* p) {
    uint32_t a;
    asm("{ .reg .u64 t; cvta.to.shared.u64 t, %1; cvt.u32.u64 %0, t; }" : "=r"(a) : "l"(p));
    return a;
}
__device__ __forceinline__ void cp_async16(uint32_t saddr, const void* gaddr) {
    asm volatile("cp.async.ca.shared.global [%0], [%1], 16;" :: "r"(saddr), "l"(gaddr));
}
__device__ __forceinline__ void cp_commit() {
    asm volatile("cp.async.commit_group;" ::: "memory");
}
__device__ __forceinline__ void cp_wait1() {
    asm volatile("cp.async.wait_group 1;" ::: "memory");
}
__device__ __forceinline__ void cp_wait0() {
    asm volatile("cp.async.wait_group 0;" ::: "memory");
}
// fp16 m16n8k16, fp32 accumulate
__device__ __forceinline__ void mma_f16(float* c, const uint32_t* a, const uint32_t* b) {
    asm volatile(
        "mma.sync.aligned.m16n8k16.row.col.f32.f16.f16.f32 "
        "{%0,%1,%2,%3}, {%4,%5,%6,%7}, {%8,%9}, {%0,%1,%2,%3};"
        : "+f"(c[0]), "+f"(c[1]), "+f"(c[2]), "+f"(c[3])
        : "r"(a[0]), "r"(a[1]), "r"(a[2]), "r"(a[3]), "r"(b[0]), "r"(b[1]));
}
__device__ __forceinline__ void ldsm_x4(uint32_t* r, uint32_t saddr) {
    asm volatile("ldmatrix.sync.aligned.m8n8.x4.shared.b16 {%0,%1,%2,%3}, [%4];"
        : "=r"(r[0]), "=r"(r[1]), "=r"(r[2]), "=r"(r[3]) : "r"(saddr));
}
__device__ __forceinline__ void ldsm_x2(uint32_t* r, uint32_t saddr) {
    asm volatile("ldmatrix.sync.aligned.m8n8.x2.shared.b16 {%0,%1}, [%2];"
        : "=r"(r[0]), "=r"(r[1]) : "r"(saddr));
}
__device__ __forceinline__ uint32_t packh2(float a, float b) {
    __half2 h = __floats2half2_rn(a, b);
    return *(uint32_t*)&h;
}

// ---------------- fused weight transpose + fp16: all 5 matrices in one launch ---
__global__ void transpose_all(const float* __restrict__ Wq, const float* __restrict__ Wk,
                              const float* __restrict__ Wv, const float* __restrict__ W1,
                              const float* __restrict__ W2,
                              __half* __restrict__ wqkvt, __half* __restrict__ w1t,
                              __half* __restrict__ w2t)
{
    __shared__ float tile[32][33];
    int bid = blockIdx.x;
    const float* W; __half* Wt; int R, N, tl;
    if (bid < 256)       { W = Wq; Wt = wqkvt;             R = DD; N = DD; tl = bid; }
    else if (bid < 512)  { W = Wk; Wt = wqkvt + DD*DD;     R = DD; N = DD; tl = bid - 256; }
    else if (bid < 768)  { W = Wv; Wt = wqkvt + 2*DD*DD;   R = DD; N = DD; tl = bid - 512; }
    else if (bid < 1792) { W = W1; Wt = w1t;               R = DD; N = FF; tl = bid - 768; }
    else                 { W = W2; Wt = w2t;               R = FF; N = DD; tl = bid - 1792; }
    int ntx = N / 32;
    int nb = (tl % ntx) * 32, rb = (tl / ntx) * 32;
    int tx = threadIdx.x, ty = threadIdx.y;   // 32 x 8
    #pragma unroll
    for (int i = 0; i < 32; i += 8)
        tile[ty + i][tx] = W[(size_t)(rb + ty + i) * N + nb + tx];
    __syncthreads();
    #pragma unroll
    for (int i = 0; i < 32; i += 8)
        Wt[(size_t)(nb + ty + i) * R + rb + tx] = __float2half_rn(tile[tx][ty + i]);
}

__global__ void concat_bias(const float* __restrict__ bq, const float* __restrict__ bk,
                            const float* __restrict__ bv, float* __restrict__ o) {
    int t = blockIdx.x * 256 + threadIdx.x;
    if (t < NQKV)
        o[t] = t < 512 ? bq[t] : (t < 1024 ? bk[t - 512] : bv[t - 1024]);
}

// ---------------- fp16 mma GEMM: C[M,N] = A[M,K] @ Bt[N,K]^T + bias -------------
// 128x128 CTA tile, KC=64 halfs, 2-stage cp.async, 256 threads, 2 CTAs/SM.
// Fragments via ldmatrix; b32 pitch 36 (144 B): LDSM rows hit 8 distinct 16B
// segments per phase -> conflict-free.
#define KC16 64
#define P32 36
#define STG_HALFS (2 * 128 * 2 * P32)
#define STG_BYTES (STG_HALFS * 2)           // 36864 B
#define GEMM_SMEM (2 * STG_BYTES)           // 73728 B

template<bool RELU, bool OUTHALF>
__global__ __launch_bounds__(256, 2)
void tc_gemm16(const __half* __restrict__ A, const __half* __restrict__ Bt,
               const float* __restrict__ bias, void* __restrict__ Cout,
               int M, int N, int K)
{
    extern __shared__ __half smh[];
    uint32_t sbase = s2u(smh);

    int t = threadIdx.x;
    int wid = t >> 5, lane = t & 31;
    int g = lane >> 2, tg = lane & 3;
    int wm = wid & 1, wn = wid >> 1;
    int brow = blockIdx.y * 128, bcol = blockIdx.x * 128;

    // ldmatrix lane roles
    int lm = lane >> 3;
    int lrowA = (lm & 1) * 8 + (lane & 7);
    int lcolA = (lm >> 1) * 4;
    int lrowB = lane & 7;
    int lcolB = (lm & 1) * 4;

    float acc[4][4][4];
    #pragma unroll
    for (int i = 0; i < 4; i++)
        #pragma unroll
        for (int j = 0; j < 4; j++)
            #pragma unroll
            for (int r = 0; r < 4; r++) acc[i][j][r] = 0.f;

    int nk = K / KC16;

    auto load_stage = [&](int s, int c) {
        uint32_t sA = sbase + (uint32_t)s * STG_BYTES;
        uint32_t sB = sA + 128u * P32 * 4u;
        const __half* ag = A + (size_t)brow * K + c * KC16;
        const __half* bg = Bt + (size_t)bcol * K + c * KC16;
        #pragma unroll
        for (int i = 0; i < 4; i++) {
            int idx = t + i * 256;
            int r = idx >> 3, cg = idx & 7;
            cp_async16(sA + (uint32_t)(r * 144 + cg * 16),
                       ag + (size_t)r * K + cg * 8);
            cp_async16(sB + (uint32_t)(r * 144 + cg * 16),
                       bg + (size_t)r * K + cg * 8);
        }
        cp_commit();
    };

    load_stage(0, 0);

    for (int c = 0; c < nk; c++) {
        if (c + 1 < nk) load_stage((c + 1) & 1, c + 1);
        if (c + 1 < nk) cp_wait1(); else cp_wait0();
        __syncthreads();

        uint32_t sA = sbase + (uint32_t)(c & 1) * STG_BYTES;
        uint32_t sB = sA + 128u * P32 * 4u;

        #pragma unroll
        for (int ks = 0; ks < 4; ks++) {
            int k0 = ks * 8;
            uint32_t af[4][4], bf[4][2];
            #pragma unroll
            for (int mt = 0; mt < 4; mt++)
                ldsm_x4(af[mt], sA + (uint32_t)((wm*64 + mt*16 + lrowA) * P32
                                                + k0 + lcolA) * 4u);
            #pragma unroll
            for (int nt = 0; nt < 4; nt++)
                ldsm_x2(bf[nt], sB + (uint32_t)((wn*32 + nt*8 + lrowB) * P32
                                                + k0 + lcolB) * 4u);
            #pragma unroll
            for (int mt = 0; mt < 4; mt++)
                #pragma unroll
                for (int nt = 0; nt < 4; nt++)
                    mma_f16(acc[mt][nt], af[mt], bf[nt]);
        }
        __syncthreads();
    }

    #pragma unroll
    for (int mt = 0; mt < 4; mt++) {
        int r0 = brow + wm * 64 + mt * 16 + g;
        #pragma unroll
        for (int nt = 0; nt < 4; nt++) {
            int col = bcol + wn * 32 + nt * 8 + tg * 2;
            float2 bv2 = *(const float2*)(bias + col);
            float v0 = acc[mt][nt][0] + bv2.x;
            float v1 = acc[mt][nt][1] + bv2.y;
            float v2 = acc[mt][nt][2] + bv2.x;
            float v3 = acc[mt][nt][3] + bv2.y;
            if (RELU) {
                v0 = fmaxf(v0, 0.f); v1 = fmaxf(v1, 0.f);
                v2 = fmaxf(v2, 0.f); v3 = fmaxf(v3, 0.f);
            }
            if (OUTHALF) {
                __half* C16 = (__half*)Cout;
                *(__half2*)(C16 + (size_t)r0 * N + col) =
                    __floats2half2_rn(v0, v1);
                *(__half2*)(C16 + (size_t)(r0 + 8) * N + col) =
                    __floats2half2_rn(v2, v3);
            } else {
                float* C = (float*)Cout;
                *(float2*)(C + (size_t)r0 * N + col)       = make_float2(v0, v1);
                *(float2*)(C + (size_t)(r0 + 8) * N + col) = make_float2(v2, v3);
            }
        }
    }
}

// ---------------- LayerNorm (fused residual; fp32 and/or fp16 outputs) ----------
template<bool W32, bool W16>
__global__ __launch_bounds__(256) void ln_kernel(
    const float* __restrict__ in1, const float* __restrict__ in2,
    const float* __restrict__ gam, const float* __restrict__ bet,
    float* __restrict__ out32, __half* __restrict__ out16)
{
    int row = blockIdx.x;
    int t = threadIdx.x;
    const float* p1 = in1 + (size_t)row * DD;
    float v0 = p1[t];
    float v1 = p1[t + 256];
    if (in2) {
        const float* p2 = in2 + (size_t)row * DD;
        v0 += p2[t];
        v1 += p2[t + 256];
    }
    __shared__ float red[8];
    float s = v0 + v1;
    #pragma unroll
    for (int o = 16; o > 0; o >>= 1) s += __shfl_xor_sync(0xffffffffu, s, o);
    if ((t & 31) == 0) red[t >> 5] = s;
    __syncthreads();
    float tot = 0.f;
    #pragma unroll
    for (int i = 0; i < 8; i++) tot += red[i];
    float mu = tot * (1.0f / DD);
    float d0 = v0 - mu, d1 = v1 - mu;
    s = d0 * d0 + d1 * d1;
    #pragma unroll
    for (int o = 16; o > 0; o >>= 1) s += __shfl_xor_sync(0xffffffffu, s, o);
    __syncthreads();
    if ((t & 31) == 0) red[t >> 5] = s;
    __syncthreads();
    tot = 0.f;
    #pragma unroll
    for (int i = 0; i < 8; i++) tot += red[i];
    float r = rsqrtf(tot * (1.0f / DD) + 1e-3f);
    float o0 = d0 * r * gam[t]       + bet[t];
    float o1 = d1 * r * gam[t + 256] + bet[t + 256];
    if (W32) {
        out32[(size_t)row * DD + t]       = o0;
        out32[(size_t)row * DD + t + 256] = o1;
    }
    if (W16) {
        out16[(size_t)row * DD + t]       = __float2half_rn(o0);
        out16[(size_t)row * DD + t + 256] = __float2half_rn(o1);
    }
}

// ---------------- tensor-core flash attention (fp16 mma + ldmatrix) -------------
#define QTILE 128
#define KTILE 64
#define AP16 36
#define ATTN_SMEM ((QTILE + KTILE + KTILE + QTILE) * AP16 * 4)   // 55296 B

__global__ __launch_bounds__(256, 2) void attn_tc(
    const __half* __restrict__ QKV, const float* __restrict__ mask,
    float* __restrict__ O)
{
    extern __shared__ uint32_t sm32[];
    uint32_t* Qs = sm32;                     // [128][36] b32 (rows q, d-pairs)
    uint32_t* Ks = Qs + QTILE * AP16;        // [64][36]  (rows k, d-pairs)
    uint32_t* Vt = Ks + KTILE * AP16;        // [64][36]  (rows d, s-pairs)
    uint32_t* Ps = Vt + KTILE * AP16;        // [128][36] (rows q, s-pairs)
    uint32_t sQ = s2u(Qs), sK = s2u(Ks), sV = s2u(Vt), sP = s2u(Ps);

    int b = blockIdx.z, h = blockIdx.y, qt = blockIdx.x;
    int t = threadIdx.x;
    int w = t >> 5, lane = t & 31;
    int g = lane >> 2, tg = lane & 3;

    int lm = lane >> 3;
    int lrowA = (lm & 1) * 8 + (lane & 7);
    int lcolA = (lm >> 1) * 4;
    int lrowB = lane & 7;
    int lcolB = (lm & 1) * 4;

    const __half* qptr  = QKV + ((size_t)(b * TT) + qt * QTILE) * NQKV + h * 64;
    const __half* kptr0 = QKV + (size_t)(b * TT) * NQKV + h * 64 + 512;
    const __half* vptr0 = QKV + (size_t)(b * TT) * NQKV + h * 64 + 1024;

    // load Q tile fp16
    #pragma unroll
    for (int i = 0; i < 4; i++) {
        int idx = t + i * 256;
        int r = idx >> 3, c = idx & 7;
        uint4 raw = *(const uint4*)(qptr + (size_t)r * NQKV + c * 8);
        *(uint4*)&Qs[r * AP16 + c * 4] = raw;
    }

    float m0 = -1e30f, m1 = -1e30f, l0 = 0.f, l1 = 0.f;
    float oacc[8][4];
    #pragma unroll
    for (int dt = 0; dt < 8; dt++)
        #pragma unroll
        for (int r = 0; r < 4; r++) oacc[dt][r] = 0.f;

    const float* mrow0 = mask + ((size_t)b * TT + qt * QTILE + w * 16 + g) * TT;
    const float* mrow1 = mrow0 + 8 * TT;
    int q0 = w * 16 + g;

    for (int kt = 0; kt < TT / KTILE; kt++) {
        // ---- load K (rows k, cols d) ----
        #pragma unroll
        for (int i = 0; i < 2; i++) {
            int idx = t + i * 256;
            int r = idx >> 3, c = idx & 7;
            uint4 raw = *(const uint4*)(kptr0 + (size_t)(kt * KTILE + r) * NQKV + c * 8);
            *(uint4*)&Ks[r * AP16 + c * 4] = raw;
        }
        // ---- load V transposed: Vt[d][s] ----
        #pragma unroll
        for (int i = 0; i < 4; i++) {
            int idx = t + i * 256;
            int d = idx & 63, s0 = (idx >> 6) * 4;
            const __half* vp = vptr0 + (size_t)(kt * KTILE + s0) * NQKV + d;
            __half2 lo = __halves2half2(vp[0], vp[NQKV]);
            __half2 hi = __halves2half2(vp[2 * NQKV], vp[3 * NQKV]);
            uint2 pk;
            pk.x = *(uint32_t*)&lo; pk.y = *(uint32_t*)&hi;
            *(uint2*)&Vt[d * AP16 + (s0 >> 1)] = pk;
        }
        __syncthreads();

        // ---- S = Q K^T ----
        float sacc[8][4];
        #pragma unroll
        for (int nt = 0; nt < 8; nt++)
            #pragma unroll
            for (int r = 0; r < 4; r++) sacc[nt][r] = 0.f;

        #pragma unroll
        for (int kc = 0; kc < 4; kc++) {
            int k0 = kc * 8;
            uint32_t af[4];
            ldsm_x4(af, sQ + (uint32_t)((w*16 + lrowA) * AP16 + k0 + lcolA) * 4u);
            #pragma unroll
            for (int nt = 0; nt < 8; nt++) {
                uint32_t bf[2];
                ldsm_x2(bf, sK + (uint32_t)((nt*8 + lrowB) * AP16 + k0 + lcolB) * 4u);
                mma_f16(sacc[nt], af, bf);
            }
        }

        // ---- scale + mask + online softmax on fragments ----
        const float* mk0 = mrow0 + kt * KTILE;
        const float* mk1 = mrow1 + kt * KTILE;
        float rm0 = -1e30f, rm1 = -1e30f;
        #pragma unroll
        for (int nt = 0; nt < 8; nt++) {
            float2 a0 = *(const float2*)(mk0 + nt * 8 + 2 * tg);
            float2 a1 = *(const float2*)(mk1 + nt * 8 + 2 * tg);
            sacc[nt][0] = sacc[nt][0] * 0.125f + (a0.x - 1.f) * 1e9f;
            sacc[nt][1] = sacc[nt][1] * 0.125f + (a0.y - 1.f) * 1e9f;
            sacc[nt][2] = sacc[nt][2] * 0.125f + (a1.x - 1.f) * 1e9f;
            sacc[nt][3] = sacc[nt][3] * 0.125f + (a1.y - 1.f) * 1e9f;
            rm0 = fmaxf(rm0, fmaxf(sacc[nt][0], sacc[nt][1]));
            rm1 = fmaxf(rm1, fmaxf(sacc[nt][2], sacc[nt][3]));
        }
        rm0 = fmaxf(rm0, __shfl_xor_sync(0xffffffffu, rm0, 1));
        rm0 = fmaxf(rm0, __shfl_xor_sync(0xffffffffu, rm0, 2));
        rm1 = fmaxf(rm1, __shfl_xor_sync(0xffffffffu, rm1, 1));
        rm1 = fmaxf(rm1, __shfl_xor_sync(0xffffffffu, rm1, 2));

        float mn0 = fmaxf(m0, rm0), mn1 = fmaxf(m1, rm1);
        float corr0 = __expf(m0 - mn0), corr1 = __expf(m1 - mn1);
        m0 = mn0; m1 = mn1;

        float rl0 = 0.f, rl1 = 0.f;
        #pragma unroll
        for (int nt = 0; nt < 8; nt++) {
            float p0 = __expf(sacc[nt][0] - mn0);
            float p1 = __expf(sacc[nt][1] - mn0);
            float p2 = __expf(sacc[nt][2] - mn1);
            float p3 = __expf(sacc[nt][3] - mn1);
            rl0 += p0 + p1;
            rl1 += p2 + p3;
            Ps[q0 * AP16 + nt * 4 + tg]       = packh2(p0, p1);
            Ps[(q0 + 8) * AP16 + nt * 4 + tg] = packh2(p2, p3);
        }
        rl0 += __shfl_xor_sync(0xffffffffu, rl0, 1);
        rl0 += __shfl_xor_sync(0xffffffffu, rl0, 2);
        rl1 += __shfl_xor_sync(0xffffffffu, rl1, 1);
        rl1 += __shfl_xor_sync(0xffffffffu, rl1, 2);
        l0 = l0 * corr0 + rl0;
        l1 = l1 * corr1 + rl1;

        #pragma unroll
        for (int dt = 0; dt < 8; dt++) {
            oacc[dt][0] *= corr0; oacc[dt][1] *= corr0;
            oacc[dt][2] *= corr1; oacc[dt][3] *= corr1;
        }
        __syncwarp();

        // ---- O += P @ V ----
        #pragma unroll
        for (int kc = 0; kc < 4; kc++) {
            int k0 = kc * 8;
            uint32_t af[4];
            ldsm_x4(af, sP + (uint32_t)((w*16 + lrowA) * AP16 + k0 + lcolA) * 4u);
            #pragma unroll
            for (int dt = 0; dt < 8; dt++) {
                uint32_t bf[2];
                ldsm_x2(bf, sV + (uint32_t)((dt*8 + lrowB) * AP16 + k0 + lcolB) * 4u);
                mma_f16(oacc[dt], af, bf);
            }
        }
        __syncthreads();
    }

    // ---- epilogue ----
    float inv0 = 1.0f / l0, inv1 = 1.0f / l1;
    float* optr = O + ((size_t)(b * TT) + qt * QTILE + w * 16 + g) * DD + h * 64;
    #pragma unroll
    for (int dt = 0; dt < 8; dt++) {
        int col = dt * 8 + 2 * tg;
        *(float2*)(optr + col) =
            make_float2(oacc[dt][0] * inv0, oacc[dt][1] * inv0);
        *(float2*)(optr + 8 * DD + col) =
            make_float2(oacc[dt][2] * inv1, oacc[dt][3] * inv1);
    }
}

// ---------------- launch ----------------
extern "C" void kernel_launch(void* const* d_in, const int* in_sizes, int n_in,
                              void* d_out, int out_size)
{
    const float* x       = (const float*)d_in[0];
    const float* mask    = (const float*)d_in[1];
    const float* ln_in_g = (const float*)d_in[2];
    const float* ln_in_b = (const float*)d_in[3];
    const float* Wq = (const float*)d_in[4];
    const float* bq = (const float*)d_in[5];
    const float* Wk = (const float*)d_in[6];
    const float* bk = (const float*)d_in[7];
    const float* Wv = (const float*)d_in[8];
    const float* bv = (const float*)d_in[9];
    const float* ln1_g = (const float*)d_in[10];
    const float* ln1_b = (const float*)d_in[11];
    const float* W1 = (const float*)d_in[12];
    const float* b1 = (const float*)d_in[13];
    const float* W2 = (const float*)d_in[14];
    const float* b2 = (const float*)d_in[15];
    const float* ln2_g = (const float*)d_in[16];
    const float* ln2_b = (const float*)d_in[17];
    float* out = (float*)d_out;

    __half *h16, *qkv16, *a16, *f116, *wqkvt, *w1t, *w2t;
    float *attnbuf, *abuf, *f2buf, *bqkv;
    cudaGetSymbolAddress((void**)&h16,     g_h16);
    cudaGetSymbolAddress((void**)&qkv16,   g_qkv16);
    cudaGetSymbolAddress((void**)&attnbuf, g_attn);
    cudaGetSymbolAddress((void**)&abuf,    g_a);
    cudaGetSymbolAddress((void**)&a16,     g_a16);
    cudaGetSymbolAddress((void**)&f116,    g_f116);
    cudaGetSymbolAddress((void**)&f2buf,   g_f2);
    cudaGetSymbolAddress((void**)&wqkvt,   g_Wqkvt16);
    cudaGetSymbolAddress((void**)&w1t,     g_W1t16);
    cudaGetSymbolAddress((void**)&w2t,     g_W2t16);
    cudaGetSymbolAddress((void**)&bqkv,    g_bqkv);

    cudaFuncSetAttribute(attn_tc,
                         cudaFuncAttributeMaxDynamicSharedMemorySize, ATTN_SMEM);
    cudaFuncSetAttribute(tc_gemm16<false, true>,
                         cudaFuncAttributeMaxDynamicSharedMemorySize, GEMM_SMEM);
    cudaFuncSetAttribute(tc_gemm16<true, true>,
                         cudaFuncAttributeMaxDynamicSharedMemorySize, GEMM_SMEM);
    cudaFuncSetAttribute(tc_gemm16<false, false>,
                         cudaFuncAttributeMaxDynamicSharedMemorySize, GEMM_SMEM);

    // fused weight transpose (5 matrices, one launch) + bias concat
    transpose_all<<<2816, dim3(32, 8)>>>(Wq, Wk, Wv, W1, W2, wqkvt, w1t, w2t);
    concat_bias<<<NQKV/256, 256>>>(bq, bk, bv, bqkv);

    // 1. h = LN(x) -> fp16 (feeds QKV GEMM only)
    ln_kernel<false, true><<<MM, 256>>>(x, nullptr, ln_in_g, ln_in_b, nullptr, h16);

    // 2. fused QKV: [M,1536] fp16 = h @ [Wq|Wk|Wv]
    tc_gemm16<false, true><<<dim3(NQKV/128, MM/128), 256, GEMM_SMEM>>>(
        h16, wqkvt, bqkv, qkv16, MM, NQKV, DD);

    // 3. masked flash attention (fp16 tensor cores)
    attn_tc<<<dim3(TT/QTILE, HH, BB), 256, ATTN_SMEM>>>(qkv16, mask, attnbuf);

    // 4. a = LN1(attn + x) -> fp32 (LN2 residual) + fp16 (FFN1 input)
    ln_kernel<true, true><<<MM, 256>>>(attnbuf, x, ln1_g, ln1_b, abuf, a16);

    // 5. FFN: f1 = relu(a@W1+b1) fp16; f2 = f1@W2+b2 fp32
    tc_gemm16<true, true><<<dim3(FF/128, MM/128), 256, GEMM_SMEM>>>(
        a16, w1t, b1, f116, MM, FF, DD);
    tc_gemm16<false, false><<<dim3(DD/128, MM/128), 256, GEMM_SMEM>>>(
        f116, w2t, b2, f2buf, MM, DD, FF);

    // 6. out = LN2(f + a)
    ln_kernel<true, false><<<MM, 256>>>(f2buf, abuf, ln2_g, ln2_b, out, nullptr);
}